// round 7
// baseline (speedup 1.0000x reference)
#include <cuda_runtime.h>
#include <cuda_bf16.h>
#include <stdint.h>

// Problem constants
#define AN   32      // agents
#define OBS  128
#define EDIM 64
#define DDIM 64
#define HHEADS 4
#define RDIM 256
#define NACT 16
#define ZDIM 192     // OBS + EDIM
#define MAXROWS (4096*32)

// Scratch buffers (aliased across pipeline stages)
__device__ float g_buf64[MAXROWS * 64];    // XE -> ATT
__device__ float g_bufH [MAXROWS * RDIM];  // H
__device__ float g_bufG [MAXROWS * RDIM];  // agg -> XR
__device__ float g_WhT  [256 * 64];
__device__ float g_WoT  [64 * 256];

__device__ __forceinline__ float sigf(float x) { return 1.0f / (1.0f + __expf(-x)); }

__device__ __forceinline__ uint32_t f2tf(float x) {
    uint32_t r;
    asm("cvt.rna.tf32.f32 %0, %1;" : "=r"(r) : "f"(x));
    return r;
}

#define MMA_TF32(d, a, b)                                                     \
    asm volatile(                                                             \
        "mma.sync.aligned.m16n8k8.row.col.f32.tf32.tf32.f32 "                 \
        "{%0,%1,%2,%3},{%4,%5,%6,%7},{%8,%9},{%0,%1,%2,%3};"                  \
        : "+f"(d[0]), "+f"(d[1]), "+f"(d[2]), "+f"(d[3])                      \
        : "r"(a[0]), "r"(a[1]), "r"(a[2]), "r"(a[3]), "r"(b[0]), "r"(b[1]))

__device__ __forceinline__ void cpa16(uint32_t dst, const float* src) {
    asm volatile("cp.async.cg.shared.global [%0], [%1], 16;"
                 :: "r"(dst), "l"(src));
}
#define CPA_COMMIT()  asm volatile("cp.async.commit_group;" ::: "memory")
#define CPA_WAIT(N)   asm volatile("cp.async.wait_group %0;" :: "n"(N) : "memory")

// ---------------------------------------------------------------------------
// k0: tiny transposes  WhT[h*64+d][e] = W_h[h][e][d];  WoT[e][k] = W_o[k][e]
// ---------------------------------------------------------------------------
__global__ void k0_prep(const float* __restrict__ Wh, const float* __restrict__ Wo,
                        float* __restrict__ WhT, float* __restrict__ WoT)
{
    int tid = blockIdx.x * blockDim.x + threadIdx.x;
    int stride = gridDim.x * blockDim.x;
    for (int i = tid; i < 256 * 64; i += stride) {
        int n = i >> 6, e = i & 63;
        int h = n >> 6, d = n & 63;
        WhT[i] = Wh[(h * 64 + e) * 64 + d];
    }
    for (int i = tid; i < 64 * 256; i += stride) {
        int e = i >> 8, k = i & 255;
        WoT[i] = Wo[k * 64 + e];
    }
}

// ---------------------------------------------------------------------------
// Generic tf32 GEMM:  C[M, N] = EPI( [A1|A2] @ W^T + bias )   (proven R4)
// ---------------------------------------------------------------------------
#define GEMM_SMEM ((2*16*136 + 2*16*72) * 4)

template<int K1, int K2, int EPI>
__global__ void __launch_bounds__(256) gemm_tn(
    const float* __restrict__ A1, const float* __restrict__ A2,
    const float* __restrict__ W,  const float* __restrict__ bias,
    float* __restrict__ C)
{
    constexpr int KT = K1 + K2;
    constexpr int NS = KT / 16;
    extern __shared__ uint32_t sg[];
    uint32_t* As = sg;                   // [2][16][136]
    uint32_t* Bs = sg + 2 * 16 * 136;    // [2][16][72]

    const int tid  = threadIdx.x;
    const int lane = tid & 31;
    const int warp = tid >> 5;
    const int wm = (warp & 3) * 32;
    const int wn = (warp >> 2) * 32;
    const int g  = lane >> 2;
    const int tg = lane & 3;
    const size_t r0 = (size_t)blockIdx.y * 128;
    const int n0 = blockIdx.x * 64;
    const int ldc = gridDim.x * 64;

    const int m0i = tid >> 2;           // 0..63
    const int kq  = (tid & 3) * 4;

    float4 ra[2], rbv;

    float acc[2][4][4];
    #pragma unroll
    for (int mt = 0; mt < 2; ++mt)
        #pragma unroll
        for (int nt = 0; nt < 4; ++nt)
            #pragma unroll
            for (int e = 0; e < 4; ++e) acc[mt][nt][e] = 0.f;

    auto ldg_stage = [&](int s) {
        const int kb = s * 16;
        #pragma unroll
        for (int i = 0; i < 2; ++i) {
            int m = m0i + i * 64;
            if (K2 == 0 || kb < K1)
                ra[i] = *(const float4*)(A1 + (r0 + m) * K1 + kb + kq);
            else
                ra[i] = *(const float4*)(A2 + (r0 + m) * K2 + (kb - K1) + kq);
        }
        rbv = *(const float4*)(W + (size_t)(n0 + m0i) * KT + kb + kq);
    };

    auto sts_stage = [&](int buf) {
        uint32_t* Ab = As + buf * (16 * 136);
        uint32_t* Bb = Bs + buf * (16 * 72);
        #pragma unroll
        for (int i = 0; i < 2; ++i) {
            int m = m0i + i * 64;
            float va[4] = {ra[i].x, ra[i].y, ra[i].z, ra[i].w};
            #pragma unroll
            for (int j = 0; j < 4; ++j) {
                int k = kq + j;
                int sw = ((k >> 2) & 3) << 3;
                Ab[k * 136 + (m ^ sw)] = f2tf(va[j]);
            }
        }
        float vb[4] = {rbv.x, rbv.y, rbv.z, rbv.w};
        #pragma unroll
        for (int j = 0; j < 4; ++j) {
            int k = kq + j;
            int sw = ((k >> 2) & 3) << 3;
            Bb[k * 72 + (m0i ^ sw)] = f2tf(vb[j]);
        }
    };

    auto compute_stage = [&](int buf) {
        const uint32_t* Ab = As + buf * (16 * 136);
        const uint32_t* Bb = Bs + buf * (16 * 72);
        #pragma unroll
        for (int k8 = 0; k8 < 2; ++k8) {
            const int kk = k8 * 8;
            const int s0 = ((2 * k8) & 3) << 3;
            const int s1 = ((2 * k8 + 1) & 3) << 3;
            uint32_t a[2][4];
            #pragma unroll
            for (int mt = 0; mt < 2; ++mt) {
                int m0 = wm + mt * 16;
                a[mt][0] = Ab[(kk + tg) * 136 + ((m0 + g) ^ s0)];
                a[mt][1] = Ab[(kk + tg) * 136 + ((m0 + g + 8) ^ s0)];
                a[mt][2] = Ab[(kk + tg + 4) * 136 + ((m0 + g) ^ s1)];
                a[mt][3] = Ab[(kk + tg + 4) * 136 + ((m0 + g + 8) ^ s1)];
            }
            uint32_t bf[4][2];
            #pragma unroll
            for (int nt = 0; nt < 4; ++nt) {
                int q0 = wn + nt * 8 + g;
                bf[nt][0] = Bb[(kk + tg) * 72 + (q0 ^ s0)];
                bf[nt][1] = Bb[(kk + tg + 4) * 72 + (q0 ^ s1)];
            }
            #pragma unroll
            for (int mt = 0; mt < 2; ++mt)
                #pragma unroll
                for (int nt = 0; nt < 4; ++nt)
                    MMA_TF32(acc[mt][nt], a[mt], bf[nt]);
        }
    };

    ldg_stage(0);
    sts_stage(0);
    __syncthreads();
    int buf = 0;
    #pragma unroll 1
    for (int s = 0; s < NS; ++s) {
        if (s < NS - 1) ldg_stage(s + 1);
        compute_stage(buf);
        if (s < NS - 1) {
            sts_stage(buf ^ 1);
            __syncthreads();
            buf ^= 1;
        }
    }

    #pragma unroll
    for (int mt = 0; mt < 2; ++mt) {
        #pragma unroll
        for (int nt = 0; nt < 4; ++nt) {
            size_t r = r0 + wm + mt * 16 + g;
            int    c = n0 + wn + nt * 8 + tg * 2;
            float v0 = acc[mt][nt][0], v1 = acc[mt][nt][1];
            float v2 = acc[mt][nt][2], v3 = acc[mt][nt][3];
            if (EPI >= 1) {
                float b0 = bias[c], b1 = bias[c + 1];
                v0 += b0; v1 += b1; v2 += b0; v3 += b1;
            }
            if (EPI == 2) {
                v0 = fmaxf(v0, 0.f); v1 = fmaxf(v1, 0.f);
                v2 = fmaxf(v2, 0.f); v3 = fmaxf(v3, 0.f);
            }
            *(float2*)(C + r * ldc + c)       = make_float2(v0, v1);
            *(float2*)(C + (r + 8) * ldc + c) = make_float2(v2, v3);
        }
    }
}

// ---------------------------------------------------------------------------
// kB: per-batch masked attention (unchanged, proven)
// ---------------------------------------------------------------------------
#define KB_HS    0
#define KB_ALPHA 8224
#define KB_SSRC  (KB_ALPHA + 4*32*33)    // 12448
#define KB_SDST  (KB_SSRC + 128)
#define KB_SAS   (KB_SDST + 128)
#define KB_SAD   (KB_SAS + 256)
#define KB_MSK   (KB_SAD + 256)          // int region
#define KB_SMEM  ((KB_MSK + 32*33) * 4)  // 57088 B

__global__ void __launch_bounds__(128) kB_attn(
    const float* __restrict__ H, const int* __restrict__ mask,
    const float* __restrict__ asrc, const float* __restrict__ adst,
    float* __restrict__ agg)
{
    extern __shared__ float smf[];
    float* Hs    = smf + KB_HS;      // pitch 257
    float* alpha = smf + KB_ALPHA;   // [4][32][33]
    float* ssrc  = smf + KB_SSRC;
    float* sdst  = smf + KB_SDST;
    float* sas   = smf + KB_SAS;
    float* sad   = smf + KB_SAD;
    int*   msk   = (int*)(smf + KB_MSK); // pitch 33

    const int tid  = threadIdx.x;
    const int lane = tid & 31;
    const int warp = tid >> 5;
    const int b    = blockIdx.x;

    const float* Hb = H + (size_t)b * (32 * 256);
    for (int i = tid; i < 32 * 256; i += 128) {
        int a = i >> 8, c = i & 255;
        Hs[a * 257 + c] = Hb[i];
    }
    for (int i = tid; i < 256; i += 128) { sas[i] = asrc[i]; sad[i] = adst[i]; }
    for (int i = tid; i < 32 * 32; i += 128) {
        int r = i >> 5, c = i & 31;
        msk[r * 33 + c] = mask[(size_t)b * (32 * 32) + i];
    }
    __syncthreads();

    {
        int hd = warp;
        float vs = 0.f, vd = 0.f;
        const float* hr = Hs + lane * 257 + hd * 64;
        #pragma unroll
        for (int d = 0; d < 64; ++d) {
            float h = hr[d];
            vs = fmaf(h, sas[hd * 64 + d], vs);
            vd = fmaf(h, sad[hd * 64 + d], vd);
        }
        ssrc[hd * 32 + lane] = vs;
        sdst[hd * 32 + lane] = vd;
    }
    __syncthreads();

    {
        int hd = tid >> 5, i = tid & 31;
        float si = ssrc[hd * 32 + i];
        float v[32];
        float m = -3.4e38f;
        #pragma unroll
        for (int j = 0; j < 32; ++j) {
            float e_ = si + sdst[hd * 32 + j];
            float l  = e_ > 0.f ? e_ : 0.2f * e_;
            if (msk[i * 33 + j] <= 0) l = -1e9f;
            v[j] = l; m = fmaxf(m, l);
        }
        float s = 0.f;
        #pragma unroll
        for (int j = 0; j < 32; ++j) { v[j] = __expf(v[j] - m); s += v[j]; }
        float inv = 1.f / s;
        #pragma unroll
        for (int j = 0; j < 32; ++j) alpha[(hd * 32 + i) * 33 + j] = v[j] * inv;
    }
    __syncthreads();

    {
        float v0[32], v1[32];
        #pragma unroll
        for (int j = 0; j < 32; ++j) {
            v0[j] = Hs[j * 257 + tid];
            v1[j] = Hs[j * 257 + tid + 128];
        }
        const int hd0 = tid >> 6;
        const int hd1 = hd0 + 2;
        float* aggb = agg + (size_t)b * (32 * 256);
        #pragma unroll 4
        for (int a = 0; a < 32; ++a) {
            const float* al0 = alpha + (hd0 * 32 + a) * 33;
            const float* al1 = alpha + (hd1 * 32 + a) * 33;
            float s0 = 0.f, s1 = 0.f;
            #pragma unroll
            for (int j = 0; j < 32; ++j) {
                s0 = fmaf(al0[j], v0[j], s0);
                s1 = fmaf(al1[j], v1[j], s1);
            }
            aggb[a * 256 + tid]       = s0;
            aggb[a * 256 + tid + 128] = s1;
        }
    }
}

// ---------------------------------------------------------------------------
// k2: GRU via tf32 MMA, cp.async pipeline, warp-local gates (no smem epilogue)
//
// Per CTA: 128 rows x 32 output cols. MMA n-space = 96, reordered so each
// warp owns ALL gates for its 16-col half:
//   warps 0-3 (wn=0):  npos 0-15 -> r cols 0-15, 16-31 -> z cols 0-15,
//                      32-47 -> n cols 0-15
//   warps 4-7 (wn=48): same for cols 16-31
// nt 0-1 = r (accumulated across both phases), nt 2-3 = z (both phases),
// nt 4-5 = n (phase-split accd[0]=xr*Wih, accd[1]=h*Whh).
// For any (row,col) one THREAD holds gr, gz, gn_i, gn_h -> gate math fully
// in registers, hh stored with STG.64. 3-buffer cp.async, 3 CTAs/SM.
// ---------------------------------------------------------------------------
#define K2_STAGEF 4480                   // floats/stage (A 128*20 + B 96*20)
#define K2_SMEM   (3 * K2_STAGEF * 4)    // 53760 B

__global__ void __launch_bounds__(256, 3) k2_gru_tc(
    const float* __restrict__ xr,  const float* __restrict__ hin,
    const float* __restrict__ Wih, const float* __restrict__ Whh,
    const float* __restrict__ bih, const float* __restrict__ bhh,
    float* __restrict__ hh_out)
{
    extern __shared__ float smf[];
    const uint32_t sbase = (uint32_t)__cvta_generic_to_shared(smf);

    const int tid  = threadIdx.x;
    const int lane = tid & 31;
    const int warp = tid >> 5;
    const int wm  = (warp & 3) * 32;     // row group
    const int wn  = (warp >> 2) * 48;    // n group (0 or 48)
    const int g   = lane >> 2;
    const int tg  = lane & 3;
    const size_t r0 = (size_t)blockIdx.y * 128;
    const int c0 = blockIdx.x * 32;

    // ---- staging assignments ----
    const int mA  = tid >> 2;            // 0..63 (second chunk: +64)
    const int k4A = (tid & 3) * 4;
    const size_t aoff0 = (r0 + mA) * 256 + k4A;
    const size_t aoff1 = (r0 + mA + 64) * 256 + k4A;
    const uint32_t adst0 = (uint32_t)(mA * 20 + k4A);
    const uint32_t adst1 = (uint32_t)((mA + 64) * 20 + k4A);
    // npos -> W row: grp = npos/16: 0,3 = r; 1,4 = z; 2,5 = n; hi half for grp>=3
    auto wrow_of = [&](int n) {
        int grp = n >> 4, cl = n & 15;
        return (grp % 3) * 256 + c0 + (grp / 3) * 16 + cl;
    };
    const int nB0 = tid >> 2;            // 0..63
    const int k4B = (tid & 3) * 4;
    const size_t boff0 = (size_t)wrow_of(nB0) * 256 + k4B;
    const size_t boff1 = (size_t)wrow_of(nB0 + 64) * 256 + k4B;
    const uint32_t bdst0 = (uint32_t)(2560 + nB0 * 20 + k4B);
    const uint32_t bdst1 = (uint32_t)(2560 + (nB0 + 64) * 20 + k4B);

    auto issue = [&](int s) {
        const int buf = s % 3;
        const int kloc = (s & 15) * 16;
        const float* Asrc = (s < 16) ? xr  : hin;
        const float* Wsrc = (s < 16) ? Wih : Whh;
        const uint32_t sb = sbase + (uint32_t)(buf * K2_STAGEF * 4);
        cpa16(sb + adst0 * 4, Asrc + aoff0 + kloc);
        cpa16(sb + adst1 * 4, Asrc + aoff1 + kloc);
        cpa16(sb + bdst0 * 4, Wsrc + boff0 + kloc);
        if (tid < 128) cpa16(sb + bdst1 * 4, Wsrc + boff1 + kloc);
        CPA_COMMIT();
    };

    // ---- accumulators ----
    float acc [2][4][4];       // [mt][nt 0-3: r0,r1,z0,z1][frag]
    float accd[2][2][2][4];    // [phase][mt][j: n0,n1][frag]
    #pragma unroll
    for (int mt = 0; mt < 2; ++mt) {
        #pragma unroll
        for (int nt = 0; nt < 4; ++nt)
            #pragma unroll
            for (int e = 0; e < 4; ++e) acc[mt][nt][e] = 0.f;
        #pragma unroll
        for (int p = 0; p < 2; ++p)
            #pragma unroll
            for (int j = 0; j < 2; ++j)
                #pragma unroll
                for (int e = 0; e < 4; ++e) accd[p][mt][j][e] = 0.f;
    }

    auto compute = [&](int buf, int ph) {
        const float* Ab = smf + buf * K2_STAGEF;
        const float* Bb = Ab + 2560;
        #pragma unroll
        for (int k8 = 0; k8 < 2; ++k8) {
            const int kk = k8 * 8;
            uint32_t a[2][4];
            #pragma unroll
            for (int mt = 0; mt < 2; ++mt) {
                int m0 = wm + mt * 16;
                a[mt][0] = __float_as_uint(Ab[(m0 + g)     * 20 + kk + tg]);
                a[mt][1] = __float_as_uint(Ab[(m0 + g + 8) * 20 + kk + tg]);
                a[mt][2] = __float_as_uint(Ab[(m0 + g)     * 20 + kk + tg + 4]);
                a[mt][3] = __float_as_uint(Ab[(m0 + g + 8) * 20 + kk + tg + 4]);
            }
            uint32_t bf[6][2];
            #pragma unroll
            for (int nt = 0; nt < 6; ++nt) {
                int q0 = wn + nt * 8 + g;
                bf[nt][0] = __float_as_uint(Bb[q0 * 20 + kk + tg]);
                bf[nt][1] = __float_as_uint(Bb[q0 * 20 + kk + tg + 4]);
            }
            #pragma unroll
            for (int mt = 0; mt < 2; ++mt) {
                #pragma unroll
                for (int nt = 0; nt < 4; ++nt)
                    MMA_TF32(acc[mt][nt], a[mt], bf[nt]);
                #pragma unroll
                for (int j = 0; j < 2; ++j) {
                    if (ph == 0) { MMA_TF32(accd[0][mt][j], a[mt], bf[4 + j]); }
                    else         { MMA_TF32(accd[1][mt][j], a[mt], bf[4 + j]); }
                }
            }
        }
    };

    // ---- pipeline: 32 stages (16 per phase), 3 smem buffers ----
    issue(0);
    issue(1);
    CPA_WAIT(1);
    __syncthreads();

    int s = 0;
    #pragma unroll 1
    for (; s < 16; ++s) {
        compute(s % 3, 0);
        if (s + 2 < 32) { issue(s + 2); CPA_WAIT(1); }
        else            { CPA_WAIT(0); }
        __syncthreads();
    }
    #pragma unroll 1
    for (; s < 32; ++s) {
        compute(s % 3, 1);
        if (s + 2 < 32) { issue(s + 2); CPA_WAIT(1); }
        else            { CPA_WAIT(0); }
        __syncthreads();
    }

    // ---- epilogue: gate math fully in registers ----
    const int colbase = c0 + (wn ? 16 : 0);
    #pragma unroll
    for (int mt = 0; mt < 2; ++mt) {
        const size_t rA = r0 + wm + mt * 16 + g;
        const size_t rB = rA + 8;
        #pragma unroll
        for (int j = 0; j < 2; ++j) {
            const int c = colbase + j * 8 + tg * 2;
            const float br0  = bih[c]       + bhh[c];
            const float br1  = bih[c + 1]   + bhh[c + 1];
            const float bz0  = bih[256 + c] + bhh[256 + c];
            const float bz1  = bih[257 + c] + bhh[257 + c];
            const float bni0 = bih[512 + c],  bni1 = bih[513 + c];
            const float bnh0 = bhh[512 + c],  bnh1 = bhh[513 + c];
            const float2 hpA = *(const float2*)(hin + rA * 256 + c);
            const float2 hpB = *(const float2*)(hin + rB * 256 + c);

            float rg, zg, ng;
            rg = sigf(acc[mt][j][0] + br0);
            zg = sigf(acc[mt][2 + j][0] + bz0);
            ng = tanhf(accd[0][mt][j][0] + bni0 + rg * (accd[1][mt][j][0] + bnh0));
            float o0 = (1.f - zg) * ng + zg * hpA.x;

            rg = sigf(acc[mt][j][1] + br1);
            zg = sigf(acc[mt][2 + j][1] + bz1);
            ng = tanhf(accd[0][mt][j][1] + bni1 + rg * (accd[1][mt][j][1] + bnh1));
            float o1 = (1.f - zg) * ng + zg * hpA.y;

            rg = sigf(acc[mt][j][2] + br0);
            zg = sigf(acc[mt][2 + j][2] + bz0);
            ng = tanhf(accd[0][mt][j][2] + bni0 + rg * (accd[1][mt][j][2] + bnh0));
            float o2 = (1.f - zg) * ng + zg * hpB.x;

            rg = sigf(acc[mt][j][3] + br1);
            zg = sigf(acc[mt][2 + j][3] + bz1);
            ng = tanhf(accd[0][mt][j][3] + bni1 + rg * (accd[1][mt][j][3] + bnh1));
            float o3 = (1.f - zg) * ng + zg * hpB.y;

            *(float2*)(hh_out + rA * 256 + c) = make_float2(o0, o1);
            *(float2*)(hh_out + rB * 256 + c) = make_float2(o2, o3);
        }
    }
}

// ---------------------------------------------------------------------------
// k3: LayerNorm + fc2 (one warp per row) — unchanged
// ---------------------------------------------------------------------------
__global__ void __launch_bounds__(256) k3_ln_fc2(
    const float* __restrict__ hh, const float* __restrict__ lng,
    const float* __restrict__ lnb, const float* __restrict__ W2,
    const float* __restrict__ b2, float* __restrict__ q, int nrows)
{
    int warp = (blockIdx.x * blockDim.x + threadIdx.x) >> 5;
    int lane = threadIdx.x & 31;
    if (warp >= nrows) return;
    const float* hr = hh + (size_t)warp * RDIM;

    float v[8];
    float s = 0.f;
    #pragma unroll
    for (int i = 0; i < 8; ++i) { v[i] = hr[lane + 32 * i]; s += v[i]; }
    #pragma unroll
    for (int o = 16; o; o >>= 1) s += __shfl_xor_sync(0xffffffffu, s, o);
    float mu = s * (1.f / 256.f);
    float vs = 0.f;
    #pragma unroll
    for (int i = 0; i < 8; ++i) { float d = v[i] - mu; vs += d * d; }
    #pragma unroll
    for (int o = 16; o; o >>= 1) vs += __shfl_xor_sync(0xffffffffu, vs, o);
    float inv = rsqrtf(vs * (1.f / 256.f) + 1e-5f);

    float hn[8];
    #pragma unroll
    for (int i = 0; i < 8; ++i)
        hn[i] = (v[i] - mu) * inv * lng[lane + 32 * i] + lnb[lane + 32 * i];

    #pragma unroll
    for (int j = 0; j < NACT; ++j) {
        float p = 0.f;
        #pragma unroll
        for (int i = 0; i < 8; ++i) p = fmaf(hn[i], W2[j * RDIM + lane + 32 * i], p);
        #pragma unroll
        for (int o = 16; o; o >>= 1) p += __shfl_xor_sync(0xffffffffu, p, o);
        if (lane == j) q[(size_t)warp * NACT + j] = p + b2[j];
    }
}

// ---------------------------------------------------------------------------
extern "C" void kernel_launch(void* const* d_in, const int* in_sizes, int n_in,
                              void* d_out, int out_size)
{
    const float* inputs = (const float*)d_in[0];
    const float* hidden = (const float*)d_in[1];
    const int*   mask   = (const int*)  d_in[2];
    const float* Wfc    = (const float*)d_in[3];
    const float* bfc    = (const float*)d_in[4];
    const float* Wh     = (const float*)d_in[5];
    const float* asrc   = (const float*)d_in[6];
    const float* adst   = (const float*)d_in[7];
    const float* Wo     = (const float*)d_in[8];
    const float* bo     = (const float*)d_in[9];
    const float* W1     = (const float*)d_in[10];
    const float* b1     = (const float*)d_in[11];
    const float* Wih    = (const float*)d_in[12];
    const float* Whh    = (const float*)d_in[13];
    const float* bih    = (const float*)d_in[14];
    const float* bhh    = (const float*)d_in[15];
    const float* lng    = (const float*)d_in[16];
    const float* lnb    = (const float*)d_in[17];
    const float* W2     = (const float*)d_in[18];
    const float* b2     = (const float*)d_in[19];

    const int B = in_sizes[0] / (AN * OBS);       // 4096
    const int nrows = B * AN;                     // 131072
    const int mblk = nrows / 128;                 // 1024

    float* q_out  = (float*)d_out;
    float* hh_out = (float*)d_out + (size_t)nrows * NACT;

    float *xe, *bh, *bg, *wht, *wot;
    cudaGetSymbolAddress((void**)&xe,  g_buf64);
    cudaGetSymbolAddress((void**)&bh,  g_bufH);
    cudaGetSymbolAddress((void**)&bg,  g_bufG);
    cudaGetSymbolAddress((void**)&wht, g_WhT);
    cudaGetSymbolAddress((void**)&wot, g_WoT);

    cudaFuncSetAttribute(kB_attn,   cudaFuncAttributeMaxDynamicSharedMemorySize, KB_SMEM);
    cudaFuncSetAttribute(k2_gru_tc, cudaFuncAttributeMaxDynamicSharedMemorySize, K2_SMEM);

    k0_prep<<<64, 256>>>(Wh, Wo, wht, wot);

    // G1: XE = inputs @ Wfc^T + bfc          [M,64]
    gemm_tn<128, 0, 1><<<dim3(1, mblk), 256, GEMM_SMEM>>>(inputs, nullptr, Wfc, bfc, xe);
    // G2: H = XE @ WhT^T                     [M,256]
    gemm_tn<64, 0, 0><<<dim3(4, mblk), 256, GEMM_SMEM>>>(xe, nullptr, wht, nullptr, bh);
    // attention: agg = softmax(mask, leaky(s_i+s_j)) @ H
    kB_attn<<<B, 128, KB_SMEM>>>(bh, mask, asrc, adst, bg);
    // G3: ATT = agg @ WoT^T + bo             [M,64] (overwrites XE)
    gemm_tn<256, 0, 1><<<dim3(1, mblk), 256, GEMM_SMEM>>>(bg, nullptr, wot, bo, xe);
    // G4: XR = relu([inputs|ATT] @ W1^T+b1)  [M,256] (overwrites agg)
    gemm_tn<128, 64, 2><<<dim3(4, mblk), 256, GEMM_SMEM>>>(inputs, xe, W1, b1, bg);
    // GRU (cp.async tf32 pipeline, warp-local gates)
    k2_gru_tc<<<dim3(8, mblk), 256, K2_SMEM>>>(bg, hidden, Wih, Whh, bih, bhh, hh_out);
    // LN + fc2
    k3_ln_fc2<<<(nrows + 7) / 8, 256>>>(hh_out, lng, lnb, W2, b2, q_out, nrows);
}

// round 8
// speedup vs baseline: 1.1042x; 1.1042x over previous
#include <cuda_runtime.h>
#include <cuda_bf16.h>
#include <stdint.h>

// Problem constants
#define AN   32      // agents
#define OBS  128
#define EDIM 64
#define DDIM 64
#define HHEADS 4
#define RDIM 256
#define NACT 16
#define ZDIM 192     // OBS + EDIM
#define MAXROWS (4096*32)

// Scratch buffers (aliased across pipeline stages)
__device__ float g_buf64[MAXROWS * 64];    // XE -> ATT
__device__ float g_bufH [MAXROWS * RDIM];  // H
__device__ float g_bufG [MAXROWS * RDIM];  // agg -> XR
__device__ float g_WhT  [256 * 64];
__device__ float g_WoT  [64 * 256];

__device__ __forceinline__ float sigf(float x) { return 1.0f / (1.0f + __expf(-x)); }

__device__ __forceinline__ uint32_t f2tf(float x) {
    uint32_t r;
    asm("cvt.rna.tf32.f32 %0, %1;" : "=r"(r) : "f"(x));
    return r;
}

#define MMA_TF32(d, a, b)                                                     \
    asm volatile(                                                             \
        "mma.sync.aligned.m16n8k8.row.col.f32.tf32.tf32.f32 "                 \
        "{%0,%1,%2,%3},{%4,%5,%6,%7},{%8,%9},{%0,%1,%2,%3};"                  \
        : "+f"(d[0]), "+f"(d[1]), "+f"(d[2]), "+f"(d[3])                      \
        : "r"(a[0]), "r"(a[1]), "r"(a[2]), "r"(a[3]), "r"(b[0]), "r"(b[1]))

#define LDSM_X4(r, addr)                                                      \
    asm volatile(                                                             \
        "ldmatrix.sync.aligned.m8n8.x4.shared.b16 {%0,%1,%2,%3}, [%4];"       \
        : "=r"((r)[0]), "=r"((r)[1]), "=r"((r)[2]), "=r"((r)[3])              \
        : "r"(addr))

__device__ __forceinline__ void cpa16(uint32_t dst, const float* src) {
    asm volatile("cp.async.cg.shared.global [%0], [%1], 16;"
                 :: "r"(dst), "l"(src));
}
#define CPA_COMMIT()  asm volatile("cp.async.commit_group;" ::: "memory")
#define CPA_WAIT(N)   asm volatile("cp.async.wait_group %0;" :: "n"(N) : "memory")

// ---------------------------------------------------------------------------
// k0: tiny transposes  WhT[h*64+d][e] = W_h[h][e][d];  WoT[e][k] = W_o[k][e]
// ---------------------------------------------------------------------------
__global__ void k0_prep(const float* __restrict__ Wh, const float* __restrict__ Wo,
                        float* __restrict__ WhT, float* __restrict__ WoT)
{
    int tid = blockIdx.x * blockDim.x + threadIdx.x;
    int stride = gridDim.x * blockDim.x;
    for (int i = tid; i < 256 * 64; i += stride) {
        int n = i >> 6, e = i & 63;
        int h = n >> 6, d = n & 63;
        WhT[i] = Wh[(h * 64 + e) * 64 + d];
    }
    for (int i = tid; i < 64 * 256; i += stride) {
        int e = i >> 8, k = i & 255;
        WoT[i] = Wo[k * 64 + e];
    }
}

// ---------------------------------------------------------------------------
// Generic tf32 GEMM:  C[M, N] = EPI( [A1|A2] @ W^T + bias )   (proven R4)
// ---------------------------------------------------------------------------
#define GEMM_SMEM ((2*16*136 + 2*16*72) * 4)

template<int K1, int K2, int EPI>
__global__ void __launch_bounds__(256) gemm_tn(
    const float* __restrict__ A1, const float* __restrict__ A2,
    const float* __restrict__ W,  const float* __restrict__ bias,
    float* __restrict__ C)
{
    constexpr int KT = K1 + K2;
    constexpr int NS = KT / 16;
    extern __shared__ uint32_t sg[];
    uint32_t* As = sg;                   // [2][16][136]
    uint32_t* Bs = sg + 2 * 16 * 136;    // [2][16][72]

    const int tid  = threadIdx.x;
    const int lane = tid & 31;
    const int warp = tid >> 5;
    const int wm = (warp & 3) * 32;
    const int wn = (warp >> 2) * 32;
    const int g  = lane >> 2;
    const int tg = lane & 3;
    const size_t r0 = (size_t)blockIdx.y * 128;
    const int n0 = blockIdx.x * 64;
    const int ldc = gridDim.x * 64;

    const int m0i = tid >> 2;           // 0..63
    const int kq  = (tid & 3) * 4;

    float4 ra[2], rbv;

    float acc[2][4][4];
    #pragma unroll
    for (int mt = 0; mt < 2; ++mt)
        #pragma unroll
        for (int nt = 0; nt < 4; ++nt)
            #pragma unroll
            for (int e = 0; e < 4; ++e) acc[mt][nt][e] = 0.f;

    auto ldg_stage = [&](int s) {
        const int kb = s * 16;
        #pragma unroll
        for (int i = 0; i < 2; ++i) {
            int m = m0i + i * 64;
            if (K2 == 0 || kb < K1)
                ra[i] = *(const float4*)(A1 + (r0 + m) * K1 + kb + kq);
            else
                ra[i] = *(const float4*)(A2 + (r0 + m) * K2 + (kb - K1) + kq);
        }
        rbv = *(const float4*)(W + (size_t)(n0 + m0i) * KT + kb + kq);
    };

    auto sts_stage = [&](int buf) {
        uint32_t* Ab = As + buf * (16 * 136);
        uint32_t* Bb = Bs + buf * (16 * 72);
        #pragma unroll
        for (int i = 0; i < 2; ++i) {
            int m = m0i + i * 64;
            float va[4] = {ra[i].x, ra[i].y, ra[i].z, ra[i].w};
            #pragma unroll
            for (int j = 0; j < 4; ++j) {
                int k = kq + j;
                int sw = ((k >> 2) & 3) << 3;
                Ab[k * 136 + (m ^ sw)] = f2tf(va[j]);
            }
        }
        float vb[4] = {rbv.x, rbv.y, rbv.z, rbv.w};
        #pragma unroll
        for (int j = 0; j < 4; ++j) {
            int k = kq + j;
            int sw = ((k >> 2) & 3) << 3;
            Bb[k * 72 + (m0i ^ sw)] = f2tf(vb[j]);
        }
    };

    auto compute_stage = [&](int buf) {
        const uint32_t* Ab = As + buf * (16 * 136);
        const uint32_t* Bb = Bs + buf * (16 * 72);
        #pragma unroll
        for (int k8 = 0; k8 < 2; ++k8) {
            const int kk = k8 * 8;
            const int s0 = ((2 * k8) & 3) << 3;
            const int s1 = ((2 * k8 + 1) & 3) << 3;
            uint32_t a[2][4];
            #pragma unroll
            for (int mt = 0; mt < 2; ++mt) {
                int m0 = wm + mt * 16;
                a[mt][0] = Ab[(kk + tg) * 136 + ((m0 + g) ^ s0)];
                a[mt][1] = Ab[(kk + tg) * 136 + ((m0 + g + 8) ^ s0)];
                a[mt][2] = Ab[(kk + tg + 4) * 136 + ((m0 + g) ^ s1)];
                a[mt][3] = Ab[(kk + tg + 4) * 136 + ((m0 + g + 8) ^ s1)];
            }
            uint32_t bf[4][2];
            #pragma unroll
            for (int nt = 0; nt < 4; ++nt) {
                int q0 = wn + nt * 8 + g;
                bf[nt][0] = Bb[(kk + tg) * 72 + (q0 ^ s0)];
                bf[nt][1] = Bb[(kk + tg + 4) * 72 + (q0 ^ s1)];
            }
            #pragma unroll
            for (int mt = 0; mt < 2; ++mt)
                #pragma unroll
                for (int nt = 0; nt < 4; ++nt)
                    MMA_TF32(acc[mt][nt], a[mt], bf[nt]);
        }
    };

    ldg_stage(0);
    sts_stage(0);
    __syncthreads();
    int buf = 0;
    #pragma unroll 1
    for (int s = 0; s < NS; ++s) {
        if (s < NS - 1) ldg_stage(s + 1);
        compute_stage(buf);
        if (s < NS - 1) {
            sts_stage(buf ^ 1);
            __syncthreads();
            buf ^= 1;
        }
    }

    #pragma unroll
    for (int mt = 0; mt < 2; ++mt) {
        #pragma unroll
        for (int nt = 0; nt < 4; ++nt) {
            size_t r = r0 + wm + mt * 16 + g;
            int    c = n0 + wn + nt * 8 + tg * 2;
            float v0 = acc[mt][nt][0], v1 = acc[mt][nt][1];
            float v2 = acc[mt][nt][2], v3 = acc[mt][nt][3];
            if (EPI >= 1) {
                float b0 = bias[c], b1 = bias[c + 1];
                v0 += b0; v1 += b1; v2 += b0; v3 += b1;
            }
            if (EPI == 2) {
                v0 = fmaxf(v0, 0.f); v1 = fmaxf(v1, 0.f);
                v2 = fmaxf(v2, 0.f); v3 = fmaxf(v3, 0.f);
            }
            *(float2*)(C + r * ldc + c)       = make_float2(v0, v1);
            *(float2*)(C + (r + 8) * ldc + c) = make_float2(v2, v3);
        }
    }
}

// ---------------------------------------------------------------------------
// kB: per-batch masked attention (unchanged, proven)
// ---------------------------------------------------------------------------
#define KB_HS    0
#define KB_ALPHA 8224
#define KB_SSRC  (KB_ALPHA + 4*32*33)    // 12448
#define KB_SDST  (KB_SSRC + 128)
#define KB_SAS   (KB_SDST + 128)
#define KB_SAD   (KB_SAS + 256)
#define KB_MSK   (KB_SAD + 256)          // int region
#define KB_SMEM  ((KB_MSK + 32*33) * 4)  // 57088 B

__global__ void __launch_bounds__(128) kB_attn(
    const float* __restrict__ H, const int* __restrict__ mask,
    const float* __restrict__ asrc, const float* __restrict__ adst,
    float* __restrict__ agg)
{
    extern __shared__ float smf[];
    float* Hs    = smf + KB_HS;      // pitch 257
    float* alpha = smf + KB_ALPHA;   // [4][32][33]
    float* ssrc  = smf + KB_SSRC;
    float* sdst  = smf + KB_SDST;
    float* sas   = smf + KB_SAS;
    float* sad   = smf + KB_SAD;
    int*   msk   = (int*)(smf + KB_MSK); // pitch 33

    const int tid  = threadIdx.x;
    const int lane = tid & 31;
    const int warp = tid >> 5;
    const int b    = blockIdx.x;

    const float* Hb = H + (size_t)b * (32 * 256);
    for (int i = tid; i < 32 * 256; i += 128) {
        int a = i >> 8, c = i & 255;
        Hs[a * 257 + c] = Hb[i];
    }
    for (int i = tid; i < 256; i += 128) { sas[i] = asrc[i]; sad[i] = adst[i]; }
    for (int i = tid; i < 32 * 32; i += 128) {
        int r = i >> 5, c = i & 31;
        msk[r * 33 + c] = mask[(size_t)b * (32 * 32) + i];
    }
    __syncthreads();

    {
        int hd = warp;
        float vs = 0.f, vd = 0.f;
        const float* hr = Hs + lane * 257 + hd * 64;
        #pragma unroll
        for (int d = 0; d < 64; ++d) {
            float h = hr[d];
            vs = fmaf(h, sas[hd * 64 + d], vs);
            vd = fmaf(h, sad[hd * 64 + d], vd);
        }
        ssrc[hd * 32 + lane] = vs;
        sdst[hd * 32 + lane] = vd;
    }
    __syncthreads();

    {
        int hd = tid >> 5, i = tid & 31;
        float si = ssrc[hd * 32 + i];
        float v[32];
        float m = -3.4e38f;
        #pragma unroll
        for (int j = 0; j < 32; ++j) {
            float e_ = si + sdst[hd * 32 + j];
            float l  = e_ > 0.f ? e_ : 0.2f * e_;
            if (msk[i * 33 + j] <= 0) l = -1e9f;
            v[j] = l; m = fmaxf(m, l);
        }
        float s = 0.f;
        #pragma unroll
        for (int j = 0; j < 32; ++j) { v[j] = __expf(v[j] - m); s += v[j]; }
        float inv = 1.f / s;
        #pragma unroll
        for (int j = 0; j < 32; ++j) alpha[(hd * 32 + i) * 33 + j] = v[j] * inv;
    }
    __syncthreads();

    {
        float v0[32], v1[32];
        #pragma unroll
        for (int j = 0; j < 32; ++j) {
            v0[j] = Hs[j * 257 + tid];
            v1[j] = Hs[j * 257 + tid + 128];
        }
        const int hd0 = tid >> 6;
        const int hd1 = hd0 + 2;
        float* aggb = agg + (size_t)b * (32 * 256);
        #pragma unroll 4
        for (int a = 0; a < 32; ++a) {
            const float* al0 = alpha + (hd0 * 32 + a) * 33;
            const float* al1 = alpha + (hd1 * 32 + a) * 33;
            float s0 = 0.f, s1 = 0.f;
            #pragma unroll
            for (int j = 0; j < 32; ++j) {
                s0 = fmaf(al0[j], v0[j], s0);
                s1 = fmaf(al1[j], v1[j], s1);
            }
            aggb[a * 256 + tid]       = s0;
            aggb[a * 256 + tid + 128] = s1;
        }
    }
}

// ---------------------------------------------------------------------------
// k2: GRU via tf32 MMA, cp.async pipeline, ldmatrix fragments, warp-local
// gates. Per CTA: 128 rows x 32 output cols. n-space 96:
//   warps 0-3 (wn=0):  npos 0-15 r cols0-15, 16-31 z cols0-15, 32-47 n cols0-15
//   warps 4-7 (wn=48): same for cols 16-31
// nt 0-1 = r (both phases), nt 2-3 = z (both), nt 4-5 = n (phase-split).
// Fragments loaded via ldmatrix.m8n8.x4 over raw fp32 bits (tf32 HW trunc).
// launch_bounds(256,2): 128 regs, no spills (R6 lesson).
// ---------------------------------------------------------------------------
#define K2_STAGEF 4480                   // floats/stage (A 128*20 + B 96*20)
#define K2_SMEM   (3 * K2_STAGEF * 4)    // 53760 B

__global__ void __launch_bounds__(256, 2) k2_gru_tc(
    const float* __restrict__ xr,  const float* __restrict__ hin,
    const float* __restrict__ Wih, const float* __restrict__ Whh,
    const float* __restrict__ bih, const float* __restrict__ bhh,
    float* __restrict__ hh_out)
{
    extern __shared__ float smf[];
    const uint32_t sbase = (uint32_t)__cvta_generic_to_shared(smf);

    const int tid  = threadIdx.x;
    const int lane = tid & 31;
    const int warp = tid >> 5;
    const int wm  = (warp & 3) * 32;     // row group
    const int wn  = (warp >> 2) * 48;    // n group (0 or 48)
    const int g   = lane >> 2;
    const int tg  = lane & 3;
    const size_t r0 = (size_t)blockIdx.y * 128;
    const int c0 = blockIdx.x * 32;

    // ---- staging assignments ----
    const int mA  = tid >> 2;            // 0..63 (second chunk: +64)
    const int k4A = (tid & 3) * 4;
    const size_t aoff0 = (r0 + mA) * 256 + k4A;
    const size_t aoff1 = (r0 + mA + 64) * 256 + k4A;
    const uint32_t adst0 = (uint32_t)(mA * 20 + k4A);
    const uint32_t adst1 = (uint32_t)((mA + 64) * 20 + k4A);
    // npos -> W row: grp = npos/16: 0,3 = r; 1,4 = z; 2,5 = n; hi half grp>=3
    auto wrow_of = [&](int n) {
        int grp = n >> 4, cl = n & 15;
        return (grp % 3) * 256 + c0 + (grp / 3) * 16 + cl;
    };
    const int nB0 = tid >> 2;            // 0..63
    const int k4B = (tid & 3) * 4;
    const size_t boff0 = (size_t)wrow_of(nB0) * 256 + k4B;
    const size_t boff1 = (size_t)wrow_of(nB0 + 64) * 256 + k4B;
    const uint32_t bdst0 = (uint32_t)(2560 + nB0 * 20 + k4B);
    const uint32_t bdst1 = (uint32_t)(2560 + (nB0 + 64) * 20 + k4B);

    auto issue = [&](int s) {
        const int buf = s % 3;
        const int kloc = (s & 15) * 16;
        const float* Asrc = (s < 16) ? xr  : hin;
        const float* Wsrc = (s < 16) ? Wih : Whh;
        const uint32_t sb = sbase + (uint32_t)(buf * K2_STAGEF * 4);
        cpa16(sb + adst0 * 4, Asrc + aoff0 + kloc);
        cpa16(sb + adst1 * 4, Asrc + aoff1 + kloc);
        cpa16(sb + bdst0 * 4, Wsrc + boff0 + kloc);
        if (tid < 128) cpa16(sb + bdst1 * 4, Wsrc + boff1 + kloc);
        CPA_COMMIT();
    };

    // ---- ldmatrix per-lane row addressing (pitch 20 floats = 80 B) ----
    const int l7 = lane & 7;
    // A x4: matrices {rows0-7,k0-3},{rows8-15,k0-3},{rows0-7,k4-7},{rows8-15,k4-7}
    const int aRow = ((lane >> 3) & 1) * 8 + l7;
    const int aK   = (lane >> 4) * 4;
    const uint32_t aAddr = sbase + (uint32_t)(((wm + aRow) * 20 + aK) * 4);
    // B x4 per nt-pair p: {n0-7,k0-3},{n0-7,k4-7},{n8-15,k0-3},{n8-15,k4-7}
    const int bRow = ((lane >> 4) & 1) * 8 + l7;
    const int bK   = ((lane >> 3) & 1) * 4;
    const uint32_t bAddr = sbase + (uint32_t)((2560 + (wn + bRow) * 20 + bK) * 4);

    // ---- accumulators ----
    float acc [2][4][4];       // [mt][nt 0-3: r0,r1,z0,z1][frag]
    float accd[2][2][2][4];    // [phase][mt][j: n0,n1][frag]
    #pragma unroll
    for (int mt = 0; mt < 2; ++mt) {
        #pragma unroll
        for (int nt = 0; nt < 4; ++nt)
            #pragma unroll
            for (int e = 0; e < 4; ++e) acc[mt][nt][e] = 0.f;
        #pragma unroll
        for (int p = 0; p < 2; ++p)
            #pragma unroll
            for (int j = 0; j < 2; ++j)
                #pragma unroll
                for (int e = 0; e < 4; ++e) accd[p][mt][j][e] = 0.f;
    }

    auto compute = [&](int buf, int ph) {
        const uint32_t bufoff = (uint32_t)(buf * K2_STAGEF * 4);
        #pragma unroll
        for (int k8 = 0; k8 < 2; ++k8) {
            const uint32_t ko = bufoff + k8 * 32;   // 8 floats = 32 B
            uint32_t a[2][4];
            LDSM_X4(a[0], aAddr + ko);
            LDSM_X4(a[1], aAddr + ko + 16 * 20 * 4);
            uint32_t bf[6][2];
            #pragma unroll
            for (int p = 0; p < 3; ++p) {
                uint32_t t[4];
                LDSM_X4(t, bAddr + ko + p * 16 * 20 * 4);
                bf[2 * p][0]     = t[0];
                bf[2 * p][1]     = t[1];
                bf[2 * p + 1][0] = t[2];
                bf[2 * p + 1][1] = t[3];
            }
            #pragma unroll
            for (int mt = 0; mt < 2; ++mt) {
                #pragma unroll
                for (int nt = 0; nt < 4; ++nt)
                    MMA_TF32(acc[mt][nt], a[mt], bf[nt]);
                #pragma unroll
                for (int j = 0; j < 2; ++j) {
                    if (ph == 0) { MMA_TF32(accd[0][mt][j], a[mt], bf[4 + j]); }
                    else         { MMA_TF32(accd[1][mt][j], a[mt], bf[4 + j]); }
                }
            }
        }
    };

    // ---- pipeline: 32 stages (16 per phase), 3 smem buffers ----
    issue(0);
    issue(1);
    CPA_WAIT(1);
    __syncthreads();

    int s = 0;
    #pragma unroll 1
    for (; s < 16; ++s) {
        compute(s % 3, 0);
        if (s + 2 < 32) { issue(s + 2); CPA_WAIT(1); }
        else            { CPA_WAIT(0); }
        __syncthreads();
    }
    #pragma unroll 1
    for (; s < 32; ++s) {
        compute(s % 3, 1);
        if (s + 2 < 32) { issue(s + 2); CPA_WAIT(1); }
        else            { CPA_WAIT(0); }
        __syncthreads();
    }

    // ---- epilogue: gate math fully in registers ----
    const int colbase = c0 + (wn ? 16 : 0);
    #pragma unroll
    for (int mt = 0; mt < 2; ++mt) {
        const size_t rA = r0 + wm + mt * 16 + g;
        const size_t rB = rA + 8;
        #pragma unroll
        for (int j = 0; j < 2; ++j) {
            const int c = colbase + j * 8 + tg * 2;
            const float br0  = bih[c]       + bhh[c];
            const float br1  = bih[c + 1]   + bhh[c + 1];
            const float bz0  = bih[256 + c] + bhh[256 + c];
            const float bz1  = bih[257 + c] + bhh[257 + c];
            const float bni0 = bih[512 + c],  bni1 = bih[513 + c];
            const float bnh0 = bhh[512 + c],  bnh1 = bhh[513 + c];
            const float2 hpA = *(const float2*)(hin + rA * 256 + c);
            const float2 hpB = *(const float2*)(hin + rB * 256 + c);

            float rg, zg, ng;
            rg = sigf(acc[mt][j][0] + br0);
            zg = sigf(acc[mt][2 + j][0] + bz0);
            ng = tanhf(accd[0][mt][j][0] + bni0 + rg * (accd[1][mt][j][0] + bnh0));
            float o0 = (1.f - zg) * ng + zg * hpA.x;

            rg = sigf(acc[mt][j][1] + br1);
            zg = sigf(acc[mt][2 + j][1] + bz1);
            ng = tanhf(accd[0][mt][j][1] + bni1 + rg * (accd[1][mt][j][1] + bnh1));
            float o1 = (1.f - zg) * ng + zg * hpA.y;

            rg = sigf(acc[mt][j][2] + br0);
            zg = sigf(acc[mt][2 + j][2] + bz0);
            ng = tanhf(accd[0][mt][j][2] + bni0 + rg * (accd[1][mt][j][2] + bnh0));
            float o2 = (1.f - zg) * ng + zg * hpB.x;

            rg = sigf(acc[mt][j][3] + br1);
            zg = sigf(acc[mt][2 + j][3] + bz1);
            ng = tanhf(accd[0][mt][j][3] + bni1 + rg * (accd[1][mt][j][3] + bnh1));
            float o3 = (1.f - zg) * ng + zg * hpB.y;

            *(float2*)(hh_out + rA * 256 + c) = make_float2(o0, o1);
            *(float2*)(hh_out + rB * 256 + c) = make_float2(o2, o3);
        }
    }
}

// ---------------------------------------------------------------------------
// k3: LayerNorm + fc2 (one warp per row) — unchanged
// ---------------------------------------------------------------------------
__global__ void __launch_bounds__(256) k3_ln_fc2(
    const float* __restrict__ hh, const float* __restrict__ lng,
    const float* __restrict__ lnb, const float* __restrict__ W2,
    const float* __restrict__ b2, float* __restrict__ q, int nrows)
{
    int warp = (blockIdx.x * blockDim.x + threadIdx.x) >> 5;
    int lane = threadIdx.x & 31;
    if (warp >= nrows) return;
    const float* hr = hh + (size_t)warp * RDIM;

    float v[8];
    float s = 0.f;
    #pragma unroll
    for (int i = 0; i < 8; ++i) { v[i] = hr[lane + 32 * i]; s += v[i]; }
    #pragma unroll
    for (int o = 16; o; o >>= 1) s += __shfl_xor_sync(0xffffffffu, s, o);
    float mu = s * (1.f / 256.f);
    float vs = 0.f;
    #pragma unroll
    for (int i = 0; i < 8; ++i) { float d = v[i] - mu; vs += d * d; }
    #pragma unroll
    for (int o = 16; o; o >>= 1) vs += __shfl_xor_sync(0xffffffffu, vs, o);
    float inv = rsqrtf(vs * (1.f / 256.f) + 1e-5f);

    float hn[8];
    #pragma unroll
    for (int i = 0; i < 8; ++i)
        hn[i] = (v[i] - mu) * inv * lng[lane + 32 * i] + lnb[lane + 32 * i];

    #pragma unroll
    for (int j = 0; j < NACT; ++j) {
        float p = 0.f;
        #pragma unroll
        for (int i = 0; i < 8; ++i) p = fmaf(hn[i], W2[j * RDIM + lane + 32 * i], p);
        #pragma unroll
        for (int o = 16; o; o >>= 1) p += __shfl_xor_sync(0xffffffffu, p, o);
        if (lane == j) q[(size_t)warp * NACT + j] = p + b2[j];
    }
}

// ---------------------------------------------------------------------------
extern "C" void kernel_launch(void* const* d_in, const int* in_sizes, int n_in,
                              void* d_out, int out_size)
{
    const float* inputs = (const float*)d_in[0];
    const float* hidden = (const float*)d_in[1];
    const int*   mask   = (const int*)  d_in[2];
    const float* Wfc    = (const float*)d_in[3];
    const float* bfc    = (const float*)d_in[4];
    const float* Wh     = (const float*)d_in[5];
    const float* asrc   = (const float*)d_in[6];
    const float* adst   = (const float*)d_in[7];
    const float* Wo     = (const float*)d_in[8];
    const float* bo     = (const float*)d_in[9];
    const float* W1     = (const float*)d_in[10];
    const float* b1     = (const float*)d_in[11];
    const float* Wih    = (const float*)d_in[12];
    const float* Whh    = (const float*)d_in[13];
    const float* bih    = (const float*)d_in[14];
    const float* bhh    = (const float*)d_in[15];
    const float* lng    = (const float*)d_in[16];
    const float* lnb    = (const float*)d_in[17];
    const float* W2     = (const float*)d_in[18];
    const float* b2     = (const float*)d_in[19];

    const int B = in_sizes[0] / (AN * OBS);       // 4096
    const int nrows = B * AN;                     // 131072
    const int mblk = nrows / 128;                 // 1024

    float* q_out  = (float*)d_out;
    float* hh_out = (float*)d_out + (size_t)nrows * NACT;

    float *xe, *bh, *bg, *wht, *wot;
    cudaGetSymbolAddress((void**)&xe,  g_buf64);
    cudaGetSymbolAddress((void**)&bh,  g_bufH);
    cudaGetSymbolAddress((void**)&bg,  g_bufG);
    cudaGetSymbolAddress((void**)&wht, g_WhT);
    cudaGetSymbolAddress((void**)&wot, g_WoT);

    cudaFuncSetAttribute(kB_attn,   cudaFuncAttributeMaxDynamicSharedMemorySize, KB_SMEM);
    cudaFuncSetAttribute(k2_gru_tc, cudaFuncAttributeMaxDynamicSharedMemorySize, K2_SMEM);

    k0_prep<<<64, 256>>>(Wh, Wo, wht, wot);

    // G1: XE = inputs @ Wfc^T + bfc          [M,64]
    gemm_tn<128, 0, 1><<<dim3(1, mblk), 256, GEMM_SMEM>>>(inputs, nullptr, Wfc, bfc, xe);
    // G2: H = XE @ WhT^T                     [M,256]
    gemm_tn<64, 0, 0><<<dim3(4, mblk), 256, GEMM_SMEM>>>(xe, nullptr, wht, nullptr, bh);
    // attention: agg = softmax(mask, leaky(s_i+s_j)) @ H
    kB_attn<<<B, 128, KB_SMEM>>>(bh, mask, asrc, adst, bg);
    // G3: ATT = agg @ WoT^T + bo             [M,64] (overwrites XE)
    gemm_tn<256, 0, 1><<<dim3(1, mblk), 256, GEMM_SMEM>>>(bg, nullptr, wot, bo, xe);
    // G4: XR = relu([inputs|ATT] @ W1^T+b1)  [M,256] (overwrites agg)
    gemm_tn<128, 64, 2><<<dim3(4, mblk), 256, GEMM_SMEM>>>(inputs, xe, W1, b1, bg);
    // GRU (cp.async tf32 pipeline, ldmatrix fragments, warp-local gates)
    k2_gru_tc<<<dim3(8, mblk), 256, K2_SMEM>>>(bg, hidden, Wih, Whh, bih, bhh, hh_out);
    // LN + fc2
    k3_ln_fc2<<<(nrows + 7) / 8, 256>>>(hh_out, lng, lnb, W2, b2, q_out, nrows);
}

// round 10
// speedup vs baseline: 1.3839x; 1.2533x over previous
#include <cuda_runtime.h>
#include <cuda_fp16.h>
#include <cuda_bf16.h>
#include <stdint.h>

// Problem constants
#define AN   32      // agents
#define OBS  128
#define EDIM 64
#define DDIM 64
#define HHEADS 4
#define RDIM 256
#define NACT 16
#define ZDIM 192     // OBS + EDIM
#define MAXROWS (4096*32)

// Scratch buffers (aliased across pipeline stages)
__device__ float g_buf64[MAXROWS * 64];    // XE -> ATT
__device__ float g_bufH [MAXROWS * RDIM];  // H
__device__ float g_bufG [MAXROWS * RDIM];  // agg
__device__ float g_WhT  [256 * 64];
__device__ float g_WoT  [64 * 256];
__device__ __align__(16) __half g_xrh  [MAXROWS * RDIM];  // XR (fp16, from G4)
__device__ __align__(16) __half g_hinh [MAXROWS * RDIM];  // hidden (fp16 copy)
__device__ __align__(16) __half g_Wih16[3 * RDIM * RDIM];
__device__ __align__(16) __half g_Whh16[3 * RDIM * RDIM];

__device__ __forceinline__ float sigf(float x) { return 1.0f / (1.0f + __expf(-x)); }

__device__ __forceinline__ uint32_t f2tf(float x) {
    uint32_t r;
    asm("cvt.rna.tf32.f32 %0, %1;" : "=r"(r) : "f"(x));
    return r;
}

#define MMA_TF32(d, a, b)                                                     \
    asm volatile(                                                             \
        "mma.sync.aligned.m16n8k8.row.col.f32.tf32.tf32.f32 "                 \
        "{%0,%1,%2,%3},{%4,%5,%6,%7},{%8,%9},{%0,%1,%2,%3};"                  \
        : "+f"(d[0]), "+f"(d[1]), "+f"(d[2]), "+f"(d[3])                      \
        : "r"(a[0]), "r"(a[1]), "r"(a[2]), "r"(a[3]), "r"(b[0]), "r"(b[1]))

#define MMA_F16(d, a, b)                                                      \
    asm volatile(                                                             \
        "mma.sync.aligned.m16n8k16.row.col.f32.f16.f16.f32 "                  \
        "{%0,%1,%2,%3},{%4,%5,%6,%7},{%8,%9},{%0,%1,%2,%3};"                  \
        : "+f"(d[0]), "+f"(d[1]), "+f"(d[2]), "+f"(d[3])                      \
        : "r"(a[0]), "r"(a[1]), "r"(a[2]), "r"(a[3]), "r"(b[0]), "r"(b[1]))

#define LDSM_X4(r, addr)                                                      \
    asm volatile(                                                             \
        "ldmatrix.sync.aligned.m8n8.x4.shared.b16 {%0,%1,%2,%3}, [%4];"       \
        : "=r"((r)[0]), "=r"((r)[1]), "=r"((r)[2]), "=r"((r)[3])              \
        : "r"(addr))

__device__ __forceinline__ void cpa16(uint32_t dst, const void* src) {
    asm volatile("cp.async.cg.shared.global [%0], [%1], 16;"
                 :: "r"(dst), "l"(src));
}
#define CPA_COMMIT()  asm volatile("cp.async.commit_group;" ::: "memory")
#define CPA_WAIT(N)   asm volatile("cp.async.wait_group %0;" :: "n"(N) : "memory")

// ---------------------------------------------------------------------------
// k0: tiny transposes + weight fp16 conversion
// ---------------------------------------------------------------------------
__global__ void k0_prep(const float* __restrict__ Wh, const float* __restrict__ Wo,
                        const float* __restrict__ Wih, const float* __restrict__ Whh,
                        float* __restrict__ WhT, float* __restrict__ WoT,
                        __half* __restrict__ Wih16, __half* __restrict__ Whh16)
{
    int tid = blockIdx.x * blockDim.x + threadIdx.x;
    int stride = gridDim.x * blockDim.x;
    for (int i = tid; i < 256 * 64; i += stride) {
        int n = i >> 6, e = i & 63;
        int h = n >> 6, d = n & 63;
        WhT[i] = Wh[(h * 64 + e) * 64 + d];
    }
    for (int i = tid; i < 64 * 256; i += stride) {
        int e = i >> 8, k = i & 255;
        WoT[i] = Wo[k * 64 + e];
    }
    for (int i = tid; i < 3 * 256 * 256; i += stride) {
        Wih16[i] = __float2half(Wih[i]);
        Whh16[i] = __float2half(Whh[i]);
    }
}

// ---------------------------------------------------------------------------
// kH: fp32 -> fp16 conversion (hidden state)
// ---------------------------------------------------------------------------
__global__ void kH_f2h(const float* __restrict__ in, __half2* __restrict__ out, int n4)
{
    int i = blockIdx.x * blockDim.x + threadIdx.x;
    int stride = gridDim.x * blockDim.x;
    for (; i < n4; i += stride) {
        float4 v = ((const float4*)in)[i];
        out[2 * i]     = __floats2half2_rn(v.x, v.y);
        out[2 * i + 1] = __floats2half2_rn(v.z, v.w);
    }
}

// ---------------------------------------------------------------------------
// Generic tf32 GEMM:  C[M, N] = EPI( [A1|A2] @ W^T + bias )   (proven R4)
// OUTH=1: store output as fp16 (half2 pairs)
// ---------------------------------------------------------------------------
#define GEMM_SMEM ((2*16*136 + 2*16*72) * 4)

template<int K1, int K2, int EPI, int OUTH>
__global__ void __launch_bounds__(256) gemm_tn(
    const float* __restrict__ A1, const float* __restrict__ A2,
    const float* __restrict__ W,  const float* __restrict__ bias,
    void* __restrict__ Cout)
{
    constexpr int KT = K1 + K2;
    constexpr int NS = KT / 16;
    extern __shared__ uint32_t sg[];
    uint32_t* As = sg;                   // [2][16][136]
    uint32_t* Bs = sg + 2 * 16 * 136;    // [2][16][72]

    const int tid  = threadIdx.x;
    const int lane = tid & 31;
    const int warp = tid >> 5;
    const int wm = (warp & 3) * 32;
    const int wn = (warp >> 2) * 32;
    const int g  = lane >> 2;
    const int tg = lane & 3;
    const size_t r0 = (size_t)blockIdx.y * 128;
    const int n0 = blockIdx.x * 64;
    const int ldc = gridDim.x * 64;

    const int m0i = tid >> 2;           // 0..63
    const int kq  = (tid & 3) * 4;

    float4 ra[2], rbv;

    float acc[2][4][4];
    #pragma unroll
    for (int mt = 0; mt < 2; ++mt)
        #pragma unroll
        for (int nt = 0; nt < 4; ++nt)
            #pragma unroll
            for (int e = 0; e < 4; ++e) acc[mt][nt][e] = 0.f;

    auto ldg_stage = [&](int s) {
        const int kb = s * 16;
        #pragma unroll
        for (int i = 0; i < 2; ++i) {
            int m = m0i + i * 64;
            if (K2 == 0 || kb < K1)
                ra[i] = *(const float4*)(A1 + (r0 + m) * K1 + kb + kq);
            else
                ra[i] = *(const float4*)(A2 + (r0 + m) * K2 + (kb - K1) + kq);
        }
        rbv = *(const float4*)(W + (size_t)(n0 + m0i) * KT + kb + kq);
    };

    auto sts_stage = [&](int buf) {
        uint32_t* Ab = As + buf * (16 * 136);
        uint32_t* Bb = Bs + buf * (16 * 72);
        #pragma unroll
        for (int i = 0; i < 2; ++i) {
            int m = m0i + i * 64;
            float va[4] = {ra[i].x, ra[i].y, ra[i].z, ra[i].w};
            #pragma unroll
            for (int j = 0; j < 4; ++j) {
                int k = kq + j;
                int sw = ((k >> 2) & 3) << 3;
                Ab[k * 136 + (m ^ sw)] = f2tf(va[j]);
            }
        }
        float vb[4] = {rbv.x, rbv.y, rbv.z, rbv.w};
        #pragma unroll
        for (int j = 0; j < 4; ++j) {
            int k = kq + j;
            int sw = ((k >> 2) & 3) << 3;
            Bb[k * 72 + (m0i ^ sw)] = f2tf(vb[j]);
        }
    };

    auto compute_stage = [&](int buf) {
        const uint32_t* Ab = As + buf * (16 * 136);
        const uint32_t* Bb = Bs + buf * (16 * 72);
        #pragma unroll
        for (int k8 = 0; k8 < 2; ++k8) {
            const int kk = k8 * 8;
            const int s0 = ((2 * k8) & 3) << 3;
            const int s1 = ((2 * k8 + 1) & 3) << 3;
            uint32_t a[2][4];
            #pragma unroll
            for (int mt = 0; mt < 2; ++mt) {
                int m0 = wm + mt * 16;
                a[mt][0] = Ab[(kk + tg) * 136 + ((m0 + g) ^ s0)];
                a[mt][1] = Ab[(kk + tg) * 136 + ((m0 + g + 8) ^ s0)];
                a[mt][2] = Ab[(kk + tg + 4) * 136 + ((m0 + g) ^ s1)];
                a[mt][3] = Ab[(kk + tg + 4) * 136 + ((m0 + g + 8) ^ s1)];
            }
            uint32_t bf[4][2];
            #pragma unroll
            for (int nt = 0; nt < 4; ++nt) {
                int q0 = wn + nt * 8 + g;
                bf[nt][0] = Bb[(kk + tg) * 72 + (q0 ^ s0)];
                bf[nt][1] = Bb[(kk + tg + 4) * 72 + (q0 ^ s1)];
            }
            #pragma unroll
            for (int mt = 0; mt < 2; ++mt)
                #pragma unroll
                for (int nt = 0; nt < 4; ++nt)
                    MMA_TF32(acc[mt][nt], a[mt], bf[nt]);
        }
    };

    ldg_stage(0);
    sts_stage(0);
    __syncthreads();
    int buf = 0;
    #pragma unroll 1
    for (int s = 0; s < NS; ++s) {
        if (s < NS - 1) ldg_stage(s + 1);
        compute_stage(buf);
        if (s < NS - 1) {
            sts_stage(buf ^ 1);
            __syncthreads();
            buf ^= 1;
        }
    }

    #pragma unroll
    for (int mt = 0; mt < 2; ++mt) {
        #pragma unroll
        for (int nt = 0; nt < 4; ++nt) {
            size_t r = r0 + wm + mt * 16 + g;
            int    c = n0 + wn + nt * 8 + tg * 2;
            float v0 = acc[mt][nt][0], v1 = acc[mt][nt][1];
            float v2 = acc[mt][nt][2], v3 = acc[mt][nt][3];
            if (EPI >= 1) {
                float b0 = bias[c], b1 = bias[c + 1];
                v0 += b0; v1 += b1; v2 += b0; v3 += b1;
            }
            if (EPI == 2) {
                v0 = fmaxf(v0, 0.f); v1 = fmaxf(v1, 0.f);
                v2 = fmaxf(v2, 0.f); v3 = fmaxf(v3, 0.f);
            }
            if (OUTH) {
                __half* Ch = (__half*)Cout;
                *(__half2*)(Ch + r * ldc + c)       = __floats2half2_rn(v0, v1);
                *(__half2*)(Ch + (r + 8) * ldc + c) = __floats2half2_rn(v2, v3);
            } else {
                float* C = (float*)Cout;
                *(float2*)(C + r * ldc + c)       = make_float2(v0, v1);
                *(float2*)(C + (r + 8) * ldc + c) = make_float2(v2, v3);
            }
        }
    }
}

// ---------------------------------------------------------------------------
// kB: per-batch masked attention (unchanged, proven)
// ---------------------------------------------------------------------------
#define KB_HS    0
#define KB_ALPHA 8224
#define KB_SSRC  (KB_ALPHA + 4*32*33)    // 12448
#define KB_SDST  (KB_SSRC + 128)
#define KB_SAS   (KB_SDST + 128)
#define KB_SAD   (KB_SAS + 256)
#define KB_MSK   (KB_SAD + 256)          // int region
#define KB_SMEM  ((KB_MSK + 32*33) * 4)  // 57088 B

__global__ void __launch_bounds__(128) kB_attn(
    const float* __restrict__ H, const int* __restrict__ mask,
    const float* __restrict__ asrc, const float* __restrict__ adst,
    float* __restrict__ agg)
{
    extern __shared__ float smf[];
    float* Hs    = smf + KB_HS;      // pitch 257
    float* alpha = smf + KB_ALPHA;   // [4][32][33]
    float* ssrc  = smf + KB_SSRC;
    float* sdst  = smf + KB_SDST;
    float* sas   = smf + KB_SAS;
    float* sad   = smf + KB_SAD;
    int*   msk   = (int*)(smf + KB_MSK); // pitch 33

    const int tid  = threadIdx.x;
    const int lane = tid & 31;
    const int warp = tid >> 5;
    const int b    = blockIdx.x;

    const float* Hb = H + (size_t)b * (32 * 256);
    for (int i = tid; i < 32 * 256; i += 128) {
        int a = i >> 8, c = i & 255;
        Hs[a * 257 + c] = Hb[i];
    }
    for (int i = tid; i < 256; i += 128) { sas[i] = asrc[i]; sad[i] = adst[i]; }
    for (int i = tid; i < 32 * 32; i += 128) {
        int r = i >> 5, c = i & 31;
        msk[r * 33 + c] = mask[(size_t)b * (32 * 32) + i];
    }
    __syncthreads();

    {
        int hd = warp;
        float vs = 0.f, vd = 0.f;
        const float* hr = Hs + lane * 257 + hd * 64;
        #pragma unroll
        for (int d = 0; d < 64; ++d) {
            float h = hr[d];
            vs = fmaf(h, sas[hd * 64 + d], vs);
            vd = fmaf(h, sad[hd * 64 + d], vd);
        }
        ssrc[hd * 32 + lane] = vs;
        sdst[hd * 32 + lane] = vd;
    }
    __syncthreads();

    {
        int hd = tid >> 5, i = tid & 31;
        float si = ssrc[hd * 32 + i];
        float v[32];
        float m = -3.4e38f;
        #pragma unroll
        for (int j = 0; j < 32; ++j) {
            float e_ = si + sdst[hd * 32 + j];
            float l  = e_ > 0.f ? e_ : 0.2f * e_;
            if (msk[i * 33 + j] <= 0) l = -1e9f;
            v[j] = l; m = fmaxf(m, l);
        }
        float s = 0.f;
        #pragma unroll
        for (int j = 0; j < 32; ++j) { v[j] = __expf(v[j] - m); s += v[j]; }
        float inv = 1.f / s;
        #pragma unroll
        for (int j = 0; j < 32; ++j) alpha[(hd * 32 + i) * 33 + j] = v[j] * inv;
    }
    __syncthreads();

    {
        float v0[32], v1[32];
        #pragma unroll
        for (int j = 0; j < 32; ++j) {
            v0[j] = Hs[j * 257 + tid];
            v1[j] = Hs[j * 257 + tid + 128];
        }
        const int hd0 = tid >> 6;
        const int hd1 = hd0 + 2;
        float* aggb = agg + (size_t)b * (32 * 256);
        #pragma unroll 4
        for (int a = 0; a < 32; ++a) {
            const float* al0 = alpha + (hd0 * 32 + a) * 33;
            const float* al1 = alpha + (hd1 * 32 + a) * 33;
            float s0 = 0.f, s1 = 0.f;
            #pragma unroll
            for (int j = 0; j < 32; ++j) {
                s0 = fmaf(al0[j], v0[j], s0);
                s1 = fmaf(al1[j], v1[j], s1);
            }
            aggb[a * 256 + tid]       = s0;
            aggb[a * 256 + tid + 128] = s1;
        }
    }
}

// ---------------------------------------------------------------------------
// k2: GRU via fp16 MMA (m16n8k16), cp.async pipeline, ldmatrix fragments,
// warp-local gates. Same structure as proven R7 tf32 kernel, but:
//   - inputs pre-converted to fp16 (xrh, hinh, Wih16, Whh16)
//   - BK = 32 halves/stage -> 16 stages total (8 per phase)
//   - smem row pitch 80 B (40 halves): conflict-free ldmatrix, same as R7
// n-space 96: warps 0-3 (wn=0) own cols 0-15 {r,z,n}, warps 4-7 cols 16-31.
// nt 0-1 = r (both phases), 2-3 = z (both), 4-5 = n (phase-split accd).
// Epilogue reads exact fp32 hidden for hprev.
// ---------------------------------------------------------------------------
#define K2H_STAGEB 17920                 // bytes/stage (A 128*80 + B 96*80)
#define K2H_SMEM   (3 * K2H_STAGEB)      // 53760 B

__global__ void __launch_bounds__(256, 2) k2_gru_f16(
    const __half* __restrict__ xrh,  const __half* __restrict__ hinh,
    const float*  __restrict__ hin,
    const __half* __restrict__ Wih,  const __half* __restrict__ Whh,
    const float*  __restrict__ bih,  const float*  __restrict__ bhh,
    float* __restrict__ hh_out)
{
    extern __shared__ __half smh[];
    const uint32_t sbase = (uint32_t)__cvta_generic_to_shared(smh);

    const int tid  = threadIdx.x;
    const int lane = tid & 31;
    const int warp = tid >> 5;
    const int wm  = (warp & 3) * 32;     // row group
    const int wn  = (warp >> 2) * 48;    // n group (0 or 48)
    const int g   = lane >> 2;
    const int tg  = lane & 3;
    const size_t r0 = (size_t)blockIdx.y * 128;
    const int c0 = blockIdx.x * 32;

    // ---- staging assignments (16B chunks = 8 halves) ----
    const int mA = tid >> 2;             // 0..63 (second chunk: +64)
    const int jA = tid & 3;
    const size_t aoff0 = (r0 + mA) * 256 + jA * 8;
    const size_t aoff1 = (r0 + mA + 64) * 256 + jA * 8;
    const uint32_t adst0 = (uint32_t)(mA * 80 + jA * 16);
    const uint32_t adst1 = (uint32_t)((mA + 64) * 80 + jA * 16);
    auto wrow_of = [&](int n) {
        int grp = n >> 4, cl = n & 15;
        return (grp % 3) * 256 + c0 + (grp / 3) * 16 + cl;
    };
    const int nB0 = tid >> 2;
    const int jB = tid & 3;
    const size_t boff0 = (size_t)wrow_of(nB0) * 256 + jB * 8;
    const size_t boff1 = (size_t)wrow_of(nB0 + 64) * 256 + jB * 8;
    const uint32_t bdst0 = (uint32_t)(10240 + nB0 * 80 + jB * 16);
    const uint32_t bdst1 = (uint32_t)(10240 + (nB0 + 64) * 80 + jB * 16);

    auto issue = [&](int s) {
        const int buf = s % 3;
        const int kloc = (s & 7) * 32;           // halves
        const __half* Asrc = (s < 8) ? xrh : hinh;
        const __half* Wsrc = (s < 8) ? Wih : Whh;
        const uint32_t sb = sbase + (uint32_t)(buf * K2H_STAGEB);
        cpa16(sb + adst0, Asrc + aoff0 + kloc);
        cpa16(sb + adst1, Asrc + aoff1 + kloc);
        cpa16(sb + bdst0, Wsrc + boff0 + kloc);
        if (tid < 128) cpa16(sb + bdst1, Wsrc + boff1 + kloc);
        CPA_COMMIT();
    };

    // ---- ldmatrix per-lane row addressing (pitch 80 B) ----
    const int l7 = lane & 7;
    const int aRow = ((lane >> 3) & 1) * 8 + l7;
    const int aKb  = (lane >> 4) * 16;
    const uint32_t aAddr = sbase + (uint32_t)((wm + aRow) * 80 + aKb);
    const int bRow = ((lane >> 4) & 1) * 8 + l7;
    const int bKb  = ((lane >> 3) & 1) * 16;
    const uint32_t bAddr = sbase + (uint32_t)(10240 + (wn + bRow) * 80 + bKb);

    // ---- accumulators ----
    float acc [2][4][4];       // [mt][nt 0-3: r0,r1,z0,z1][frag]
    float accd[2][2][2][4];    // [phase][mt][j: n0,n1][frag]
    #pragma unroll
    for (int mt = 0; mt < 2; ++mt) {
        #pragma unroll
        for (int nt = 0; nt < 4; ++nt)
            #pragma unroll
            for (int e = 0; e < 4; ++e) acc[mt][nt][e] = 0.f;
        #pragma unroll
        for (int p = 0; p < 2; ++p)
            #pragma unroll
            for (int j = 0; j < 2; ++j)
                #pragma unroll
                for (int e = 0; e < 4; ++e) accd[p][mt][j][e] = 0.f;
    }

    auto compute = [&](int buf, int ph) {
        const uint32_t bufoff = (uint32_t)(buf * K2H_STAGEB);
        #pragma unroll
        for (int ks = 0; ks < 2; ++ks) {
            const uint32_t ko = bufoff + ks * 32;   // 16 halves = 32 B
            uint32_t a[2][4];
            LDSM_X4(a[0], aAddr + ko);
            LDSM_X4(a[1], aAddr + ko + 16 * 80);
            uint32_t bf[6][2];
            #pragma unroll
            for (int p = 0; p < 3; ++p) {
                uint32_t t[4];
                LDSM_X4(t, bAddr + ko + p * 16 * 80);
                bf[2 * p][0]     = t[0];
                bf[2 * p][1]     = t[1];
                bf[2 * p + 1][0] = t[2];
                bf[2 * p + 1][1] = t[3];
            }
            #pragma unroll
            for (int mt = 0; mt < 2; ++mt) {
                #pragma unroll
                for (int nt = 0; nt < 4; ++nt)
                    MMA_F16(acc[mt][nt], a[mt], bf[nt]);
                #pragma unroll
                for (int j = 0; j < 2; ++j) {
                    if (ph == 0) { MMA_F16(accd[0][mt][j], a[mt], bf[4 + j]); }
                    else         { MMA_F16(accd[1][mt][j], a[mt], bf[4 + j]); }
                }
            }
        }
    };

    // ---- pipeline: 16 stages (8 per phase), 3 smem buffers ----
    issue(0);
    issue(1);
    CPA_WAIT(1);
    __syncthreads();

    int s = 0;
    #pragma unroll 1
    for (; s < 8; ++s) {
        compute(s % 3, 0);
        if (s + 2 < 16) { issue(s + 2); CPA_WAIT(1); }
        else            { CPA_WAIT(0); }
        __syncthreads();
    }
    #pragma unroll 1
    for (; s < 16; ++s) {
        compute(s % 3, 1);
        if (s + 2 < 16) { issue(s + 2); CPA_WAIT(1); }
        else            { CPA_WAIT(0); }
        __syncthreads();
    }

    // ---- epilogue: gate math fully in registers ----
    const int colbase = c0 + (wn ? 16 : 0);
    #pragma unroll
    for (int mt = 0; mt < 2; ++mt) {
        const size_t rA = r0 + wm + mt * 16 + g;
        const size_t rB = rA + 8;
        #pragma unroll
        for (int j = 0; j < 2; ++j) {
            const int c = colbase + j * 8 + tg * 2;
            const float br0  = bih[c]       + bhh[c];
            const float br1  = bih[c + 1]   + bhh[c + 1];
            const float bz0  = bih[256 + c] + bhh[256 + c];
            const float bz1  = bih[257 + c] + bhh[257 + c];
            const float bni0 = bih[512 + c],  bni1 = bih[513 + c];
            const float bnh0 = bhh[512 + c],  bnh1 = bhh[513 + c];
            const float2 hpA = *(const float2*)(hin + rA * 256 + c);
            const float2 hpB = *(const float2*)(hin + rB * 256 + c);

            float rg, zg, ng;
            rg = sigf(acc[mt][j][0] + br0);
            zg = sigf(acc[mt][2 + j][0] + bz0);
            ng = tanhf(accd[0][mt][j][0] + bni0 + rg * (accd[1][mt][j][0] + bnh0));
            float o0 = (1.f - zg) * ng + zg * hpA.x;

            rg = sigf(acc[mt][j][1] + br1);
            zg = sigf(acc[mt][2 + j][1] + bz1);
            ng = tanhf(accd[0][mt][j][1] + bni1 + rg * (accd[1][mt][j][1] + bnh1));
            float o1 = (1.f - zg) * ng + zg * hpA.y;

            rg = sigf(acc[mt][j][2] + br0);
            zg = sigf(acc[mt][2 + j][2] + bz0);
            ng = tanhf(accd[0][mt][j][2] + bni0 + rg * (accd[1][mt][j][2] + bnh0));
            float o2 = (1.f - zg) * ng + zg * hpB.x;

            rg = sigf(acc[mt][j][3] + br1);
            zg = sigf(acc[mt][2 + j][3] + bz1);
            ng = tanhf(accd[0][mt][j][3] + bni1 + rg * (accd[1][mt][j][3] + bnh1));
            float o3 = (1.f - zg) * ng + zg * hpB.y;

            *(float2*)(hh_out + rA * 256 + c) = make_float2(o0, o1);
            *(float2*)(hh_out + rB * 256 + c) = make_float2(o2, o3);
        }
    }
}

// ---------------------------------------------------------------------------
// k3: LayerNorm + fc2 (one warp per row) — unchanged
// ---------------------------------------------------------------------------
__global__ void __launch_bounds__(256) k3_ln_fc2(
    const float* __restrict__ hh, const float* __restrict__ lng,
    const float* __restrict__ lnb, const float* __restrict__ W2,
    const float* __restrict__ b2, float* __restrict__ q, int nrows)
{
    int warp = (blockIdx.x * blockDim.x + threadIdx.x) >> 5;
    int lane = threadIdx.x & 31;
    if (warp >= nrows) return;
    const float* hr = hh + (size_t)warp * RDIM;

    float v[8];
    float s = 0.f;
    #pragma unroll
    for (int i = 0; i < 8; ++i) { v[i] = hr[lane + 32 * i]; s += v[i]; }
    #pragma unroll
    for (int o = 16; o; o >>= 1) s += __shfl_xor_sync(0xffffffffu, s, o);
    float mu = s * (1.f / 256.f);
    float vs = 0.f;
    #pragma unroll
    for (int i = 0; i < 8; ++i) { float d = v[i] - mu; vs += d * d; }
    #pragma unroll
    for (int o = 16; o; o >>= 1) vs += __shfl_xor_sync(0xffffffffu, vs, o);
    float inv = rsqrtf(vs * (1.f / 256.f) + 1e-5f);

    float hn[8];
    #pragma unroll
    for (int i = 0; i < 8; ++i)
        hn[i] = (v[i] - mu) * inv * lng[lane + 32 * i] + lnb[lane + 32 * i];

    #pragma unroll
    for (int j = 0; j < NACT; ++j) {
        float p = 0.f;
        #pragma unroll
        for (int i = 0; i < 8; ++i) p = fmaf(hn[i], W2[j * RDIM + lane + 32 * i], p);
        #pragma unroll
        for (int o = 16; o; o >>= 1) p += __shfl_xor_sync(0xffffffffu, p, o);
        if (lane == j) q[(size_t)warp * NACT + j] = p + b2[j];
    }
}

// ---------------------------------------------------------------------------
extern "C" void kernel_launch(void* const* d_in, const int* in_sizes, int n_in,
                              void* d_out, int out_size)
{
    const float* inputs = (const float*)d_in[0];
    const float* hidden = (const float*)d_in[1];
    const int*   mask   = (const int*)  d_in[2];
    const float* Wfc    = (const float*)d_in[3];
    const float* bfc    = (const float*)d_in[4];
    const float* Wh     = (const float*)d_in[5];
    const float* asrc   = (const float*)d_in[6];
    const float* adst   = (const float*)d_in[7];
    const float* Wo     = (const float*)d_in[8];
    const float* bo     = (const float*)d_in[9];
    const float* W1     = (const float*)d_in[10];
    const float* b1     = (const float*)d_in[11];
    const float* Wih    = (const float*)d_in[12];
    const float* Whh    = (const float*)d_in[13];
    const float* bih    = (const float*)d_in[14];
    const float* bhh    = (const float*)d_in[15];
    const float* lng    = (const float*)d_in[16];
    const float* lnb    = (const float*)d_in[17];
    const float* W2     = (const float*)d_in[18];
    const float* b2     = (const float*)d_in[19];

    const int B = in_sizes[0] / (AN * OBS);       // 4096
    const int nrows = B * AN;                     // 131072
    const int mblk = nrows / 128;                 // 1024

    float* q_out  = (float*)d_out;
    float* hh_out = (float*)d_out + (size_t)nrows * NACT;

    float *xe, *bh, *bg, *wht, *wot;
    __half *xrh, *hinh, *wih16, *whh16;
    cudaGetSymbolAddress((void**)&xe,    g_buf64);
    cudaGetSymbolAddress((void**)&bh,    g_bufH);
    cudaGetSymbolAddress((void**)&bg,    g_bufG);
    cudaGetSymbolAddress((void**)&wht,   g_WhT);
    cudaGetSymbolAddress((void**)&wot,   g_WoT);
    cudaGetSymbolAddress((void**)&xrh,   g_xrh);
    cudaGetSymbolAddress((void**)&hinh,  g_hinh);
    cudaGetSymbolAddress((void**)&wih16, g_Wih16);
    cudaGetSymbolAddress((void**)&whh16, g_Whh16);

    cudaFuncSetAttribute(kB_attn,    cudaFuncAttributeMaxDynamicSharedMemorySize, KB_SMEM);
    cudaFuncSetAttribute(k2_gru_f16, cudaFuncAttributeMaxDynamicSharedMemorySize, K2H_SMEM);

    k0_prep<<<64, 256>>>(Wh, Wo, Wih, Whh, wht, wot, wih16, whh16);
    // hidden -> fp16 copy (independent of GAT chain)
    kH_f2h<<<4096, 256>>>(hidden, (__half2*)hinh, nrows * RDIM / 4);

    // G1: XE = inputs @ Wfc^T + bfc          [M,64]
    gemm_tn<128, 0, 1, 0><<<dim3(1, mblk), 256, GEMM_SMEM>>>(inputs, nullptr, Wfc, bfc, xe);
    // G2: H = XE @ WhT^T                     [M,256]
    gemm_tn<64, 0, 0, 0><<<dim3(4, mblk), 256, GEMM_SMEM>>>(xe, nullptr, wht, nullptr, bh);
    // attention: agg = softmax(mask, leaky(s_i+s_j)) @ H
    kB_attn<<<B, 128, KB_SMEM>>>(bh, mask, asrc, adst, bg);
    // G3: ATT = agg @ WoT^T + bo             [M,64] (overwrites XE)
    gemm_tn<256, 0, 1, 0><<<dim3(1, mblk), 256, GEMM_SMEM>>>(bg, nullptr, wot, bo, xe);
    // G4: XR = relu([inputs|ATT] @ W1^T+b1)  [M,256] fp16 output
    gemm_tn<128, 64, 2, 1><<<dim3(4, mblk), 256, GEMM_SMEM>>>(inputs, xe, W1, b1, xrh);
    // GRU (fp16 MMA pipeline, warp-local gates)
    k2_gru_f16<<<dim3(8, mblk), 256, K2H_SMEM>>>(xrh, hinh, hidden, wih16, whh16,
                                                 bih, bhh, hh_out);
    // LN + fc2
    k3_ln_fc2<<<(nrows + 7) / 8, 256>>>(hh_out, lng, lnb, W2, b2, q_out, nrows);
}